// round 2
// baseline (speedup 1.0000x reference)
#include <cuda_runtime.h>

#define B_SZ 16384
#define D_SZ 17
#define H_SZ 256
#define E_SZ 64
#define SLOPE 0.01f

#define MB 64          // batch rows per CTA in kernel 1
#define KC 32          // K-chunk staged in smem
#define HS 260         // padded stride for activation buffers (bank-conflict-free)

// token scratch (B, D, E) fp32 — static device array (no allocation)
__device__ float g_tokens[(size_t)B_SZ * D_SZ * E_SZ];

__device__ __forceinline__ float lrelu(float v) { return v >= 0.f ? v : SLOPE * v; }

// ---------------------------------------------------------------------------
// Kernel 1: per (batch tile, subnet i): fused 1->H->H->H->E, tokens to gmem
// ---------------------------------------------------------------------------
__global__ void __launch_bounds__(256, 1) subnet_kernel(
    const float* __restrict__ x,  const float* __restrict__ W1, const float* __restrict__ b1,
    const float* __restrict__ Wm, const float* __restrict__ bm,
    const float* __restrict__ Wf, const float* __restrict__ bf)
{
    extern __shared__ float smem[];
    float* hA   = smem;                 // MB*HS
    float* hB   = hA + MB * HS;         // MB*HS
    float* Wbuf = hB + MB * HS;         // KC*H_SZ = 8192 floats (also used for Wf chunks)
    float* xs   = Wbuf + KC * H_SZ;     // MB

    const int t  = threadIdx.x;
    const int i  = blockIdx.y;
    const int r0 = blockIdx.x * MB;

    if (t < MB) xs[t] = x[(size_t)(r0 + t) * D_SZ + i];
    __syncthreads();

    const int tx = t & 31;   // col group: cols tx*8 .. tx*8+7
    const int ty = t >> 5;   // row group: rows ty*8 .. ty*8+7

    // ---- first layer: outer product + bias + lrelu -> hA ----
    {
        float w1v[8], b1v[8];
        #pragma unroll
        for (int c = 0; c < 8; c++) {
            w1v[c] = W1[i * H_SZ + tx * 8 + c];
            b1v[c] = b1[i * H_SZ + tx * 8 + c];
        }
        #pragma unroll
        for (int r = 0; r < 8; r++) {
            float xv = xs[ty * 8 + r];
            #pragma unroll
            for (int c = 0; c < 8; c++)
                hA[(ty * 8 + r) * HS + tx * 8 + c] = lrelu(xv * w1v[c] + b1v[c]);
        }
    }
    __syncthreads();

    // ---- two middle H x H layers ----
    float* src = hA;
    float* dst = hB;
    for (int l = 0; l < 2; l++) {
        const float* W    = Wm + (size_t)(l * D_SZ + i) * H_SZ * H_SZ;
        const float* bias = bm + (size_t)(l * D_SZ + i) * H_SZ;

        float acc[8][8];
        #pragma unroll
        for (int r = 0; r < 8; r++)
            #pragma unroll
            for (int c = 0; c < 8; c++) acc[r][c] = 0.f;

        for (int kc = 0; kc < H_SZ / KC; kc++) {
            // stage weight chunk [KC x H] into smem (coalesced float4)
            const float4* Wg  = reinterpret_cast<const float4*>(W + (size_t)kc * KC * H_SZ);
            float4*       Wb4 = reinterpret_cast<float4*>(Wbuf);
            #pragma unroll
            for (int q = 0; q < 8; q++) Wb4[t + 256 * q] = Wg[t + 256 * q];
            __syncthreads();

            #pragma unroll
            for (int kk = 0; kk < KC; kk++) {
                float a[8];
                #pragma unroll
                for (int r = 0; r < 8; r++)
                    a[r] = src[(ty * 8 + r) * HS + kc * KC + kk];
                float4 w0 = *reinterpret_cast<const float4*>(&Wbuf[kk * H_SZ + tx * 8]);
                float4 w1_ = *reinterpret_cast<const float4*>(&Wbuf[kk * H_SZ + tx * 8 + 4]);
                float wv[8] = {w0.x, w0.y, w0.z, w0.w, w1_.x, w1_.y, w1_.z, w1_.w};
                #pragma unroll
                for (int r = 0; r < 8; r++)
                    #pragma unroll
                    for (int c = 0; c < 8; c++)
                        acc[r][c] += a[r] * wv[c];
            }
            __syncthreads();
        }

        // epilogue: bias + lrelu -> dst
        float bb[8];
        #pragma unroll
        for (int c = 0; c < 8; c++) bb[c] = bias[tx * 8 + c];
        #pragma unroll
        for (int r = 0; r < 8; r++) {
            float4 v0, v1;
            v0.x = lrelu(acc[r][0] + bb[0]);
            v0.y = lrelu(acc[r][1] + bb[1]);
            v0.z = lrelu(acc[r][2] + bb[2]);
            v0.w = lrelu(acc[r][3] + bb[3]);
            v1.x = lrelu(acc[r][4] + bb[4]);
            v1.y = lrelu(acc[r][5] + bb[5]);
            v1.z = lrelu(acc[r][6] + bb[6]);
            v1.w = lrelu(acc[r][7] + bb[7]);
            *reinterpret_cast<float4*>(&dst[(ty * 8 + r) * HS + tx * 8])     = v0;
            *reinterpret_cast<float4*>(&dst[(ty * 8 + r) * HS + tx * 8 + 4]) = v1;
        }
        __syncthreads();
        float* tmp = src; src = dst; dst = tmp;
    }

    // ---- final projection H -> E, tokens (no activation) ----
    {
        const float* W   = Wf + (size_t)i * H_SZ * E_SZ;
        const int tx2 = t & 7;    // cols tx2*8 .. +7
        const int ty2 = t >> 3;   // rows ty2*2, ty2*2+1

        float acc2[2][8];
        #pragma unroll
        for (int r = 0; r < 2; r++)
            #pragma unroll
            for (int c = 0; c < 8; c++) acc2[r][c] = 0.f;

        for (int kc = 0; kc < 2; kc++) {
            const float4* Wg  = reinterpret_cast<const float4*>(W + (size_t)kc * 128 * E_SZ);
            float4*       Wb4 = reinterpret_cast<float4*>(Wbuf);
            #pragma unroll
            for (int q = 0; q < 8; q++) Wb4[t + 256 * q] = Wg[t + 256 * q];
            __syncthreads();

            #pragma unroll 16
            for (int kk = 0; kk < 128; kk++) {
                float a0 = src[(ty2 * 2 + 0) * HS + kc * 128 + kk];
                float a1 = src[(ty2 * 2 + 1) * HS + kc * 128 + kk];
                float4 w0 = *reinterpret_cast<const float4*>(&Wbuf[kk * E_SZ + tx2 * 8]);
                float4 w1_ = *reinterpret_cast<const float4*>(&Wbuf[kk * E_SZ + tx2 * 8 + 4]);
                float wv[8] = {w0.x, w0.y, w0.z, w0.w, w1_.x, w1_.y, w1_.z, w1_.w};
                #pragma unroll
                for (int c = 0; c < 8; c++) {
                    acc2[0][c] += a0 * wv[c];
                    acc2[1][c] += a1 * wv[c];
                }
            }
            __syncthreads();
        }

        float bb2[8];
        #pragma unroll
        for (int c = 0; c < 8; c++) bb2[c] = bf[i * E_SZ + tx2 * 8 + c];
        #pragma unroll
        for (int r = 0; r < 2; r++) {
            int row = r0 + ty2 * 2 + r;
            float4 v0, v1;
            v0.x = acc2[r][0] + bb2[0];
            v0.y = acc2[r][1] + bb2[1];
            v0.z = acc2[r][2] + bb2[2];
            v0.w = acc2[r][3] + bb2[3];
            v1.x = acc2[r][4] + bb2[4];
            v1.y = acc2[r][5] + bb2[5];
            v1.z = acc2[r][6] + bb2[6];
            v1.w = acc2[r][7] + bb2[7];
            float* tp = g_tokens + ((size_t)row * D_SZ + i) * E_SZ + tx2 * 8;
            *reinterpret_cast<float4*>(tp)     = v0;
            *reinterpret_cast<float4*>(tp + 4) = v1;
        }
    }
}

// ---------------------------------------------------------------------------
// Kernel 2: attention + pool + final projection. One warp per batch row.
// ---------------------------------------------------------------------------
#define RPW 4      // rows per warp
#define QS  68     // padded stride for per-row 17x64 buffers

__global__ void __launch_bounds__(256, 1) attn_kernel(
    const float* __restrict__ Wq, const float* __restrict__ bq,
    const float* __restrict__ Wk, const float* __restrict__ bk,
    const float* __restrict__ Wv, const float* __restrict__ bv,
    const float* __restrict__ Wo, const float* __restrict__ bo,
    const float* __restrict__ Wfc, const float* __restrict__ bfc,
    float* __restrict__ out)
{
    extern __shared__ float smem[];
    // weights staged transposed-padded: Ws[e*65 + j] = W[e*64 + j]
    float* Wsq = smem;                 // 64*65 = 4160
    float* Wsk = Wsq + 4160;
    float* Wsv = Wsk + 4160;
    float* Wso = Wsv + 4160;
    float* bqs = Wso + 4160;           // 64
    float* bks = bqs + 64;
    float* bvs = bks + 64;
    float* bos = bvs + 64;
    float* wfcs = bos + 64;            // 64
    float* warpbuf = wfcs + 64;        // 8 warps * (4*17*QS + 64)

    const int t = threadIdx.x;

    #pragma unroll
    for (int q = 0; q < 16; q++) {
        int idx = t + 256 * q;         // 4096 per matrix
        int e = idx >> 6, j = idx & 63;
        Wsq[e * 65 + j] = Wq[idx];
        Wsk[e * 65 + j] = Wk[idx];
        Wsv[e * 65 + j] = Wv[idx];
        Wso[e * 65 + j] = Wo[idx];
    }
    if (t < 64) {
        bqs[t] = bq[t]; bks[t] = bk[t]; bvs[t] = bv[t]; bos[t] = bo[t];
        wfcs[t] = Wfc[t];
    }
    __syncthreads();

    const int wid = t >> 5, lane = t & 31;
    float* wb  = warpbuf + wid * (4 * D_SZ * QS + 64);
    float* tok = wb;                   // 17*QS — reused for attended output
    float* qs  = tok + D_SZ * QS;
    float* ks  = qs + D_SZ * QS;
    float* vs  = ks + D_SZ * QS;
    float* ms  = vs + D_SZ * QS;       // 64 (pooled mean)
    const float bfc0 = bfc[0];

    for (int rr = 0; rr < RPW; rr++) {
        const int row = (blockIdx.x * 8 + wid) * RPW + rr;
        const float* trow = g_tokens + (size_t)row * (D_SZ * E_SZ);

        // load tokens for this row
        #pragma unroll
        for (int u = 0; u < 34; u++) {
            int o = u * 32 + lane;
            tok[(o >> 6) * QS + (o & 63)] = trow[o];
        }
        __syncwarp();

        // fused Q/K/V projections (torch Linear: y = x @ W.T + b)
        #pragma unroll
        for (int u = 0; u < 34; u++) {
            int o = u * 32 + lane;
            int ii = o >> 6, e = o & 63;
            float aq = bqs[e], ak = bks[e], av = bvs[e];
            const float* tr = tok + ii * QS;
            #pragma unroll
            for (int j = 0; j < 64; j++) {
                float tv = tr[j];
                aq += tv * Wsq[e * 65 + j];
                ak += tv * Wsk[e * 65 + j];
                av += tv * Wsv[e * 65 + j];
            }
            qs[ii * QS + e] = aq;
            ks[ii * QS + e] = ak;
            vs[ii * QS + e] = av;
        }
        __syncwarp();

        // attention per (head, query) pair; writes attended output into tok
        #pragma unroll
        for (int u = 0; u < 3; u++) {
            int p = u * 32 + lane;
            if (p < 68) {
                int h = p / 17, i1 = p % 17;
                const float* qv = qs + i1 * QS + h * 16;
                float s[17];
                float smax = -1e30f;
                #pragma unroll
                for (int i2 = 0; i2 < 17; i2++) {
                    const float* kv = ks + i2 * QS + h * 16;
                    float d = 0.f;
                    #pragma unroll
                    for (int j = 0; j < 16; j++) d += qv[j] * kv[j];
                    d *= 0.25f;  // 1/sqrt(hd=16)
                    s[i2] = d;
                    smax = fmaxf(smax, d);
                }
                float den = 0.f;
                #pragma unroll
                for (int i2 = 0; i2 < 17; i2++) { s[i2] = __expf(s[i2] - smax); den += s[i2]; }
                float inv = 1.f / den;
                #pragma unroll
                for (int j = 0; j < 16; j++) {
                    float a = 0.f;
                    #pragma unroll
                    for (int i2 = 0; i2 < 17; i2++)
                        a += s[i2] * vs[i2 * QS + h * 16 + j];
                    tok[i1 * QS + h * 16 + j] = a * inv;
                }
            }
        }
        __syncwarp();

        // mean over tokens BEFORE Wo (pool commutes with linear): ms[e]
        #pragma unroll
        for (int half = 0; half < 2; half++) {
            int e = lane + 32 * half;
            float sm = 0.f;
            #pragma unroll
            for (int ii = 0; ii < D_SZ; ii++) sm += tok[ii * QS + e];
            ms[e] = sm * (1.f / 17.f);
        }
        __syncwarp();

        // y = ms @ Wo.T + bo, then dot with Wfc, warp-reduce, lrelu
        float partial = 0.f;
        #pragma unroll
        for (int half = 0; half < 2; half++) {
            int e = lane + 32 * half;
            float y = bos[e];
            #pragma unroll
            for (int j = 0; j < 64; j++) y += ms[j] * Wso[e * 65 + j];
            partial += y * wfcs[e];
        }
        #pragma unroll
        for (int off = 16; off; off >>= 1)
            partial += __shfl_down_sync(0xffffffffu, partial, off);
        if (lane == 0) out[row] = lrelu(partial + bfc0);
        __syncwarp();
    }
}

// ---------------------------------------------------------------------------
extern "C" void kernel_launch(void* const* d_in, const int* in_sizes, int n_in,
                              void* d_out, int out_size)
{
    const float* x   = (const float*)d_in[0];
    const float* W1  = (const float*)d_in[1];
    const float* b1  = (const float*)d_in[2];
    const float* Wm  = (const float*)d_in[3];
    const float* bm  = (const float*)d_in[4];
    const float* Wf  = (const float*)d_in[5];
    const float* bf  = (const float*)d_in[6];
    const float* Wq  = (const float*)d_in[7];
    const float* bq  = (const float*)d_in[8];
    const float* Wk  = (const float*)d_in[9];
    const float* bk  = (const float*)d_in[10];
    const float* Wv  = (const float*)d_in[11];
    const float* bv  = (const float*)d_in[12];
    const float* Wo  = (const float*)d_in[13];
    const float* bo  = (const float*)d_in[14];
    const float* Wfc = (const float*)d_in[15];
    const float* bfc = (const float*)d_in[16];
    float* out = (float*)d_out;

    const int k1_smem = (2 * MB * HS + KC * H_SZ + MB) * (int)sizeof(float);          // 166,144 B
    const int k2_smem = (4 * 4160 + 4 * 64 + 64 + 8 * (4 * D_SZ * QS + 64)) * (int)sizeof(float); // 217,856 B

    cudaFuncSetAttribute(subnet_kernel, cudaFuncAttributeMaxDynamicSharedMemorySize, k1_smem);
    cudaFuncSetAttribute(attn_kernel,   cudaFuncAttributeMaxDynamicSharedMemorySize, k2_smem);

    dim3 g1(B_SZ / MB, D_SZ);
    subnet_kernel<<<g1, 256, k1_smem>>>(x, W1, b1, Wm, bm, Wf, bf);

    attn_kernel<<<B_SZ / (8 * RPW), 256, k2_smem>>>(Wq, bq, Wk, bk, Wv, bv, Wo, bo, Wfc, bfc, out);
}

// round 3
// speedup vs baseline: 1.3307x; 1.3307x over previous
#include <cuda_runtime.h>
#include <cstdint>

#define SLOPE 0.01f
#define Dn 17
#define Hn 256
#define En 64
#define NCB 136          // combined proj cols: q 0-63, k 64-127, vs 128-131, pad
#define KC 16            // K-chunk
#define HS 260           // padded activation stride
#define MB 64            // batch rows per CTA (kernel 1)
#define Bn 16384

// ---- static device scratch (no allocation) ----
__device__ __align__(16) float g_q [(size_t)Bn * Dn * En];
__device__ __align__(16) float g_k [(size_t)Bn * Dn * En];
__device__ __align__(16) float g_vs[(size_t)Bn * Dn * 4];
__device__ __align__(16) float g_Wcomb[Dn * Hn * NCB];
__device__ __align__(16) float g_bcomb[Dn * NCB];
__device__ float g_cv[4 * En];
__device__ float g_dv[4];
__device__ float g_const;

__device__ __forceinline__ float lrelu(float v) { return v >= 0.f ? v : SLOPE * v; }

// packed f32x2 helpers (Blackwell FFMA2 path)
#define FMA2(d, a, b, c) asm("fma.rn.f32x2 %0, %1, %2, %3;" : "=l"(d) : "l"(a), "l"(b), "l"(c))
__device__ __forceinline__ unsigned long long dupf(float v) {
    unsigned long long r; unsigned u = __float_as_uint(v);
    asm("mov.b64 %0, {%1, %1};" : "=l"(r) : "r"(u));
    return r;
}
__device__ __forceinline__ float2 unpk(unsigned long long p) {
    unsigned lo, hi;
    asm("mov.b64 {%0, %1}, %2;" : "=r"(lo), "=r"(hi) : "l"(p));
    return make_float2(__uint_as_float(lo), __uint_as_float(hi));
}

__device__ __forceinline__ void cpa16(const float* smem_dst, const float* gsrc) {
    uint32_t s = (uint32_t)__cvta_generic_to_shared(smem_dst);
    asm volatile("cp.async.cg.shared.global [%0], [%1], 16;" :: "r"(s), "l"(gsrc));
}
#define CPCOMMIT() asm volatile("cp.async.commit_group;")
#define CPWAIT(n)  asm volatile("cp.async.wait_group %0;" :: "n"(n))

// ---------------------------------------------------------------------------
// setup1: u = Wo^T Wfc ; cv_h ; dv_h ; const  (1 block, 64 threads)
// ---------------------------------------------------------------------------
__global__ void setup1_kernel(const float* __restrict__ Wv, const float* __restrict__ bv,
                              const float* __restrict__ Wo, const float* __restrict__ bo,
                              const float* __restrict__ Wfc, const float* __restrict__ bfc)
{
    __shared__ float us[64];
    int t = threadIdx.x;
    float s = 0.f;
    for (int e = 0; e < 64; e++) s += Wo[e * 64 + t] * Wfc[e];
    us[t] = s;
    __syncthreads();
    for (int h = 0; h < 4; h++) {
        float c = 0.f;
        for (int j = 0; j < 16; j++) c += Wv[(h * 16 + j) * 64 + t] * us[h * 16 + j];
        g_cv[h * 64 + t] = c;
    }
    if (t < 4) {
        float dsum = 0.f;
        for (int j = 0; j < 16; j++) dsum += bv[t * 16 + j] * us[t * 16 + j];
        g_dv[t] = dsum;
    }
    if (t == 0) {
        float c = bfc[0];
        for (int e = 0; e < 64; e++) c += bo[e] * Wfc[e];
        g_const = c;
    }
}

// ---------------------------------------------------------------------------
// setup2: Wcomb[i] = [Wf@Wq^T | Wf@Wk^T | Wf@cv | 0], bcomb   (grid 17)
// ---------------------------------------------------------------------------
__global__ void setup2_kernel(const float* __restrict__ Wf, const float* __restrict__ bf,
                              const float* __restrict__ Wq, const float* __restrict__ bq,
                              const float* __restrict__ Wk, const float* __restrict__ bk)
{
    __shared__ float Wqs[4096], Wks[4096], cvs[256];
    int t = threadIdx.x, i = blockIdx.x;
    #pragma unroll
    for (int u = 0; u < 16; u++) {
        int idx = t + 256 * u;
        Wqs[idx] = Wq[idx];
        Wks[idx] = Wk[idx];
    }
    cvs[t] = g_cv[t];
    __syncthreads();

    int k = t;
    float wf[64];
    #pragma unroll
    for (int tt = 0; tt < 64; tt++) wf[tt] = Wf[((size_t)i * 256 + k) * 64 + tt];
    float* dst = g_Wcomb + ((size_t)i * 256 + k) * NCB;
    for (int e = 0; e < 64; e++) {
        float sq = 0.f, sk = 0.f;
        #pragma unroll
        for (int tt = 0; tt < 64; tt++) { sq += wf[tt] * Wqs[e * 64 + tt]; sk += wf[tt] * Wks[e * 64 + tt]; }
        dst[e] = sq; dst[64 + e] = sk;
    }
    #pragma unroll
    for (int h = 0; h < 4; h++) {
        float sv = 0.f;
        #pragma unroll
        for (int tt = 0; tt < 64; tt++) sv += wf[tt] * cvs[h * 64 + tt];
        dst[128 + h] = sv;
    }
    dst[132] = dst[133] = dst[134] = dst[135] = 0.f;

    if (t < NCB) {
        float v;
        if (t < 64) {
            v = bq[t];
            for (int tt = 0; tt < 64; tt++) v += bf[i * 64 + tt] * Wqs[t * 64 + tt];
        } else if (t < 128) {
            int e = t - 64; v = bk[e];
            for (int tt = 0; tt < 64; tt++) v += bf[i * 64 + tt] * Wks[e * 64 + tt];
        } else if (t < 132) {
            int h = t - 128; v = g_dv[h];
            for (int tt = 0; tt < 64; tt++) v += bf[i * 64 + tt] * cvs[h * 64 + tt];
        } else v = 0.f;
        g_bcomb[i * NCB + t] = v;
    }
}

// ---------------------------------------------------------------------------
// Kernel 1: fused subnet 1->H->H->H->(q,k,vs) with FFMA2 + cp.async pipeline
// ---------------------------------------------------------------------------
__global__ void __launch_bounds__(256, 2) subnet_kernel(
    const float* __restrict__ x,  const float* __restrict__ W1, const float* __restrict__ b1,
    const float* __restrict__ Wm, const float* __restrict__ bm)
{
    extern __shared__ float smem[];
    float* hA   = smem;                  // MB*HS = 16640
    float* Wbuf = hA + MB * HS;          // 2 * KC*Hn = 8192
    float* xs   = Wbuf + 2 * KC * Hn;    // MB

    const int t  = threadIdx.x;
    const int i  = blockIdx.y;
    const int r0 = blockIdx.x * MB;
    const int tx = t & 31, ty = t >> 5;

    if (t < MB) xs[t] = x[(size_t)(r0 + t) * Dn + i];

    // prefetch layer-0 weight chunk 0 -> buf 0
    {
        const float* W = Wm + (size_t)i * Hn * Hn;
        #pragma unroll
        for (int j = 0; j < 4; j++) {
            int idx = t + 256 * j;
            cpa16(Wbuf + idx * 4, W + idx * 4);
        }
        CPCOMMIT();
    }
    __syncthreads();

    // ---- first layer: outer product ----
    {
        float w1v[8], b1v[8];
        #pragma unroll
        for (int c = 0; c < 8; c++) {
            w1v[c] = W1[i * Hn + tx * 8 + c];
            b1v[c] = b1[i * Hn + tx * 8 + c];
        }
        #pragma unroll
        for (int r = 0; r < 8; r++) {
            float xv = xs[ty * 8 + r];
            #pragma unroll
            for (int c = 0; c < 8; c++)
                hA[(ty * 8 + r) * HS + tx * 8 + c] = lrelu(xv * w1v[c] + b1v[c]);
        }
    }
    // no explicit sync: the chunk loop's first wait+sync orders hA

    // ---- two middle H x H layers (in-place on hA) ----
    #pragma unroll 1
    for (int l = 0; l < 2; l++) {
        unsigned long long acc[8][4];
        #pragma unroll
        for (int r = 0; r < 8; r++)
            #pragma unroll
            for (int p = 0; p < 4; p++) acc[r][p] = 0ull;

        #pragma unroll 1
        for (int c = 0; c < 16; c++) {
            // stage next chunk
            if (c < 15) {
                const float* W = Wm + (size_t)(l * Dn + i) * Hn * Hn + (size_t)(c + 1) * KC * Hn;
                float* dstb = Wbuf + ((c + 1) & 1) * (KC * Hn);
                #pragma unroll
                for (int j = 0; j < 4; j++) {
                    int idx = t + 256 * j;
                    cpa16(dstb + idx * 4, W + idx * 4);
                }
                CPCOMMIT(); CPWAIT(1);
            } else if (l == 0) {
                const float* W = Wm + (size_t)(Dn + i) * Hn * Hn;
                #pragma unroll
                for (int j = 0; j < 4; j++) {
                    int idx = t + 256 * j;
                    cpa16(Wbuf + idx * 4, W + idx * 4);
                }
                CPCOMMIT(); CPWAIT(1);
            } else {
                const float* W = g_Wcomb + (size_t)i * Hn * NCB;
                for (int idx = t; idx < 544; idx += 256)
                    cpa16(Wbuf + idx * 4, W + idx * 4);
                CPCOMMIT(); CPWAIT(1);
            }
            __syncthreads();

            const float* wb = Wbuf + (c & 1) * (KC * Hn);
            #pragma unroll
            for (int kk2 = 0; kk2 < 8; kk2++) {
                float2 av[8];
                #pragma unroll
                for (int r = 0; r < 8; r++)
                    av[r] = *(const float2*)&hA[(ty * 8 + r) * HS + c * KC + kk2 * 2];
                ulonglong2 wa = *(const ulonglong2*)&wb[(kk2 * 2) * Hn + tx * 8];
                ulonglong2 wb2 = *(const ulonglong2*)&wb[(kk2 * 2) * Hn + tx * 8 + 4];
                ulonglong2 wc = *(const ulonglong2*)&wb[(kk2 * 2 + 1) * Hn + tx * 8];
                ulonglong2 wd = *(const ulonglong2*)&wb[(kk2 * 2 + 1) * Hn + tx * 8 + 4];
                #pragma unroll
                for (int r = 0; r < 8; r++) {
                    unsigned long long ax = dupf(av[r].x), ay = dupf(av[r].y);
                    FMA2(acc[r][0], ax, wa.x, acc[r][0]);
                    FMA2(acc[r][1], ax, wa.y, acc[r][1]);
                    FMA2(acc[r][2], ax, wb2.x, acc[r][2]);
                    FMA2(acc[r][3], ax, wb2.y, acc[r][3]);
                    FMA2(acc[r][0], ay, wc.x, acc[r][0]);
                    FMA2(acc[r][1], ay, wc.y, acc[r][1]);
                    FMA2(acc[r][2], ay, wd.x, acc[r][2]);
                    FMA2(acc[r][3], ay, wd.y, acc[r][3]);
                }
            }
            __syncthreads();
        }

        // epilogue: bias + lrelu, in-place
        const float* bias = bm + (size_t)(l * Dn + i) * Hn;
        #pragma unroll
        for (int r = 0; r < 8; r++) {
            #pragma unroll
            for (int p = 0; p < 4; p++) {
                float2 f = unpk(acc[r][p]);
                float2 bb = *(const float2*)&bias[tx * 8 + 2 * p];
                f.x = lrelu(f.x + bb.x);
                f.y = lrelu(f.y + bb.y);
                *(float2*)&hA[(ty * 8 + r) * HS + tx * 8 + 2 * p] = f;
            }
        }
        __syncthreads();
    }

    // ---- final combined projection H -> 132 (q,k,vs) ----
    {
        const int tx4 = t & 15;     // col group: 8 cols at tx4*8 (0..127)
        const int ty4 = t >> 4;     // rows ty4*4 .. +3
        const int vrow = t >> 2;    // vs: row 0..63
        const int vcol = t & 3;     // vs: col 0..3

        unsigned long long facc[4][4];
        #pragma unroll
        for (int r = 0; r < 4; r++)
            #pragma unroll
            for (int p = 0; p < 4; p++) facc[r][p] = 0ull;
        float vacc = 0.f;

        #pragma unroll 1
        for (int c = 0; c < 16; c++) {
            if (c < 15) {
                const float* W = g_Wcomb + (size_t)i * Hn * NCB + (size_t)(c + 1) * KC * NCB;
                float* dstb = Wbuf + ((c + 1) & 1) * (KC * Hn);
                for (int idx = t; idx < 544; idx += 256)
                    cpa16(dstb + idx * 4, W + idx * 4);
                CPCOMMIT(); CPWAIT(1);
            } else {
                CPWAIT(0);
            }
            __syncthreads();

            const float* wb = Wbuf + (c & 1) * (KC * Hn);
            #pragma unroll
            for (int kk2 = 0; kk2 < 8; kk2++) {
                float2 av[4];
                #pragma unroll
                for (int r = 0; r < 4; r++)
                    av[r] = *(const float2*)&hA[(ty4 * 4 + r) * HS + c * KC + kk2 * 2];
                ulonglong2 wa = *(const ulonglong2*)&wb[(kk2 * 2) * NCB + tx4 * 8];
                ulonglong2 wb2 = *(const ulonglong2*)&wb[(kk2 * 2) * NCB + tx4 * 8 + 4];
                ulonglong2 wc = *(const ulonglong2*)&wb[(kk2 * 2 + 1) * NCB + tx4 * 8];
                ulonglong2 wd = *(const ulonglong2*)&wb[(kk2 * 2 + 1) * NCB + tx4 * 8 + 4];
                #pragma unroll
                for (int r = 0; r < 4; r++) {
                    unsigned long long ax = dupf(av[r].x), ay = dupf(av[r].y);
                    FMA2(facc[r][0], ax, wa.x, facc[r][0]);
                    FMA2(facc[r][1], ax, wa.y, facc[r][1]);
                    FMA2(facc[r][2], ax, wb2.x, facc[r][2]);
                    FMA2(facc[r][3], ax, wb2.y, facc[r][3]);
                    FMA2(facc[r][0], ay, wc.x, facc[r][0]);
                    FMA2(facc[r][1], ay, wc.y, facc[r][1]);
                    FMA2(facc[r][2], ay, wd.x, facc[r][2]);
                    FMA2(facc[r][3], ay, wd.y, facc[r][3]);
                }
                // vs part (cols 128..131): 1 output per thread
                float a0 = hA[vrow * HS + c * KC + kk2 * 2];
                float a1 = hA[vrow * HS + c * KC + kk2 * 2 + 1];
                vacc += a0 * wb[(kk2 * 2) * NCB + 128 + vcol];
                vacc += a1 * wb[(kk2 * 2 + 1) * NCB + 128 + vcol];
            }
            __syncthreads();
        }

        // store q/k
        const float* bc = g_bcomb + i * NCB;
        #pragma unroll
        for (int r = 0; r < 4; r++) {
            int row = r0 + ty4 * 4 + r;
            #pragma unroll
            for (int p = 0; p < 4; p++) {
                int col = tx4 * 8 + 2 * p;
                float2 f = unpk(facc[r][p]);
                float2 bb = *(const float2*)&bc[col];
                f.x += bb.x; f.y += bb.y;
                if (col < 64)
                    *(float2*)&g_q[((size_t)row * Dn + i) * En + col] = f;
                else
                    *(float2*)&g_k[((size_t)row * Dn + i) * En + (col - 64)] = f;
            }
        }
        // store vs
        {
            int row = r0 + vrow;
            g_vs[((size_t)row * Dn + i) * 4 + vcol] = vacc + bc[128 + vcol];
        }
    }
}

// ---------------------------------------------------------------------------
// Kernel 2: attention-lite. One warp per batch row.
// scores from q,k; softmax; weighted sum of per-token head scalars vs.
// ---------------------------------------------------------------------------
#define QS2 68
__global__ void __launch_bounds__(256, 2) attn_kernel(float* __restrict__ out)
{
    extern __shared__ float smem[];
    const int t = threadIdx.x, wid = t >> 5, lane = t & 31;
    float* qs  = smem + wid * (2 * Dn * QS2 + 68);
    float* ks  = qs + Dn * QS2;
    float* vss = ks + Dn * QS2;                     // 68 floats: [i2*4 + h]

    const int row = blockIdx.x * 8 + wid;
    const float* qr = g_q + (size_t)row * (Dn * En);
    const float* kr = g_k + (size_t)row * (Dn * En);

    #pragma unroll
    for (int u = 0; u < 34; u++) {
        int o = u * 32 + lane;
        int ii = o >> 6, e = o & 63;
        qs[ii * QS2 + e] = qr[o];
        ks[ii * QS2 + e] = kr[o];
    }
    #pragma unroll
    for (int u = 0; u < 3; u++) {
        int p = u * 32 + lane;
        if (p < 68) vss[p] = g_vs[(size_t)row * 68 + p];
    }
    __syncwarp();

    float partial = 0.f;
    #pragma unroll
    for (int u = 0; u < 3; u++) {
        int p = u * 32 + lane;
        if (p < 68) {
            int h = p / 17, i1 = p - h * 17;
            const float* qv = qs + i1 * QS2 + h * 16;
            float s[17], smax = -1e30f;
            #pragma unroll
            for (int i2 = 0; i2 < 17; i2++) {
                const float* kv = ks + i2 * QS2 + h * 16;
                float d = 0.f;
                #pragma unroll
                for (int j = 0; j < 16; j++) d += qv[j] * kv[j];
                d *= 0.25f;
                s[i2] = d;
                smax = fmaxf(smax, d);
            }
            float den = 0.f, num = 0.f;
            #pragma unroll
            for (int i2 = 0; i2 < 17; i2++) {
                float e = __expf(s[i2] - smax);
                den += e;
                num += e * vss[i2 * 4 + h];
            }
            partial += num / den;
        }
    }
    #pragma unroll
    for (int off = 16; off; off >>= 1)
        partial += __shfl_down_sync(0xffffffffu, partial, off);
    if (lane == 0) out[row] = lrelu(partial * (1.f / 17.f) + g_const);
}

// ---------------------------------------------------------------------------
extern "C" void kernel_launch(void* const* d_in, const int* in_sizes, int n_in,
                              void* d_out, int out_size)
{
    const float* x   = (const float*)d_in[0];
    const float* W1  = (const float*)d_in[1];
    const float* b1  = (const float*)d_in[2];
    const float* Wm  = (const float*)d_in[3];
    const float* bm  = (const float*)d_in[4];
    const float* Wf  = (const float*)d_in[5];
    const float* bf  = (const float*)d_in[6];
    const float* Wq  = (const float*)d_in[7];
    const float* bq  = (const float*)d_in[8];
    const float* Wk  = (const float*)d_in[9];
    const float* bk  = (const float*)d_in[10];
    const float* Wv  = (const float*)d_in[11];
    const float* bv  = (const float*)d_in[12];
    const float* Wo  = (const float*)d_in[13];
    const float* bo  = (const float*)d_in[14];
    const float* Wfc = (const float*)d_in[15];
    const float* bfc = (const float*)d_in[16];
    float* out = (float*)d_out;

    const int k1_smem = (MB * HS + 2 * KC * Hn + MB) * (int)sizeof(float);       // 99,584 B
    const int k2_smem = 8 * (2 * Dn * QS2 + 68) * (int)sizeof(float);            // 76,160 B

    static int configured = 0;
    if (!configured) {
        cudaFuncSetAttribute(subnet_kernel, cudaFuncAttributeMaxDynamicSharedMemorySize, k1_smem);
        cudaFuncSetAttribute(attn_kernel,   cudaFuncAttributeMaxDynamicSharedMemorySize, k2_smem);
        configured = 1;
    }

    setup1_kernel<<<1, 64>>>(Wv, bv, Wo, bo, Wfc, bfc);
    setup2_kernel<<<Dn, 256>>>(Wf, bf, Wq, bq, Wk, bk);

    dim3 g1(Bn / MB, Dn);
    subnet_kernel<<<g1, 256, k1_smem>>>(x, W1, b1, Wm, bm);

    attn_kernel<<<Bn / 8, 256, k2_smem>>>(out);
}

// round 5
// speedup vs baseline: 3.7958x; 2.8524x over previous
#include <cuda_runtime.h>
#include <cuda_bf16.h>
#include <cstdint>

#define SLOPE 0.01f
#define Dn 17
#define Hn 256
#define En 64
#define NCB 136
#define Bn 16384

// smem byte offsets (main kernel)
#define SM_X     0        // 128 floats
#define SM_W1    512      // 256 floats
#define SM_B1    1536     // 256 floats
#define SM_BM0   2560     // 256 floats
#define SM_BM1   3584     // 256 floats
#define SM_BC    4608     // 136 floats
#define SM_BBUF  5248     // 2 x 8704 B double buffer
#define SM_ALO   22784    // 2 x 65536 A-lo fragment buffers
#define SM_TOTAL (22784 + 131072)

// ---- static device scratch (no allocation) ----
__device__ float g_q [(size_t)Bn * Dn * En];
__device__ float g_k [(size_t)Bn * Dn * En];
__device__ float g_vs[(size_t)Bn * Dn * 4];
__device__ float g_Wcomb[Dn * Hn * NCB];
__device__ float g_bcomb[Dn * NCB];
__device__ float g_cv[4 * En];
__device__ float g_dv[4];
__device__ float g_const;
// fragment-ordered bf16 weight blobs (hi/lo split)
// mid: per mat (l*17+i): uint2[((h*16+kt)*2+s)*16+ntl)*32+lane], 32768 uint2
__device__ uint2 g_Bmid[(size_t)2 * Dn * 32768];
// fin: per i: uint2[((kt*2+s)*17+nt)*32+lane], 17408 uint2
__device__ uint2 g_Bfin[(size_t)Dn * 17408];

__device__ __forceinline__ float lrelu(float v) { return v >= 0.f ? v : SLOPE * v; }

// pack two f32 -> bf16x2 (lo -> bits[15:0], hi -> bits[31:16])
__device__ __forceinline__ uint32_t pk(float lo, float hi) {
    uint32_t r;
    asm("cvt.rn.bf16x2.f32 %0, %1, %2;" : "=r"(r) : "f"(hi), "f"(lo));
    return r;
}
__device__ __forceinline__ float relo(uint32_t p, float v) { return v - __uint_as_float(p << 16); }
__device__ __forceinline__ float rehi(uint32_t p, float v) { return v - __uint_as_float(p & 0xffff0000u); }

__device__ __forceinline__ void mma16816(float* d, const uint32_t* a, uint32_t b0, uint32_t b1) {
    asm volatile(
        "mma.sync.aligned.m16n8k16.row.col.f32.bf16.bf16.f32 "
        "{%0,%1,%2,%3}, {%4,%5,%6,%7}, {%8,%9}, {%0,%1,%2,%3};"
        : "+f"(d[0]), "+f"(d[1]), "+f"(d[2]), "+f"(d[3])
        : "r"(a[0]), "r"(a[1]), "r"(a[2]), "r"(a[3]), "r"(b0), "r"(b1));
}

__device__ __forceinline__ void cpa16(void* sdst, const void* gsrc) {
    uint32_t s = (uint32_t)__cvta_generic_to_shared(sdst);
    asm volatile("cp.async.cg.shared.global [%0], [%1], 16;" :: "r"(s), "l"(gsrc));
}
#define CPCOMMIT() asm volatile("cp.async.commit_group;")
#define CPWAIT(n)  asm volatile("cp.async.wait_group %0;" :: "n"(n))

// ============================ setup kernels ============================
__global__ void setup1_kernel(const float* __restrict__ Wv, const float* __restrict__ bv,
                              const float* __restrict__ Wo, const float* __restrict__ bo,
                              const float* __restrict__ Wfc, const float* __restrict__ bfc)
{
    __shared__ float us[64];
    int t = threadIdx.x;
    float s = 0.f;
    for (int e = 0; e < 64; e++) s += Wo[e * 64 + t] * Wfc[e];
    us[t] = s;
    __syncthreads();
    for (int h = 0; h < 4; h++) {
        float c = 0.f;
        for (int j = 0; j < 16; j++) c += Wv[(h * 16 + j) * 64 + t] * us[h * 16 + j];
        g_cv[h * 64 + t] = c;
    }
    if (t < 4) {
        float dsum = 0.f;
        for (int j = 0; j < 16; j++) dsum += bv[t * 16 + j] * us[t * 16 + j];
        g_dv[t] = dsum;
    }
    if (t == 0) {
        float c = bfc[0];
        for (int e = 0; e < 64; e++) c += bo[e] * Wfc[e];
        g_const = c;
    }
}

__global__ void setup2_kernel(const float* __restrict__ Wf, const float* __restrict__ bf,
                              const float* __restrict__ Wq, const float* __restrict__ bq,
                              const float* __restrict__ Wk, const float* __restrict__ bk)
{
    __shared__ float Wqs[4096], Wks[4096], cvs[256];
    int t = threadIdx.x, i = blockIdx.x;
    #pragma unroll
    for (int u = 0; u < 16; u++) {
        int idx = t + 256 * u;
        Wqs[idx] = Wq[idx];
        Wks[idx] = Wk[idx];
    }
    cvs[t] = g_cv[t];
    __syncthreads();

    int k = t;
    float wf[64];
    #pragma unroll
    for (int tt = 0; tt < 64; tt++) wf[tt] = Wf[((size_t)i * 256 + k) * 64 + tt];
    float* dst = g_Wcomb + ((size_t)i * 256 + k) * NCB;
    for (int e = 0; e < 64; e++) {
        float sq = 0.f, sk = 0.f;
        #pragma unroll
        for (int tt = 0; tt < 64; tt++) { sq += wf[tt] * Wqs[e * 64 + tt]; sk += wf[tt] * Wks[e * 64 + tt]; }
        dst[e] = sq; dst[64 + e] = sk;
    }
    #pragma unroll
    for (int h = 0; h < 4; h++) {
        float sv = 0.f;
        #pragma unroll
        for (int tt = 0; tt < 64; tt++) sv += wf[tt] * cvs[h * 64 + tt];
        dst[128 + h] = sv;
    }
    dst[132] = dst[133] = dst[134] = dst[135] = 0.f;

    if (t < NCB) {
        float v;
        if (t < 64) {
            v = bq[t];
            for (int tt = 0; tt < 64; tt++) v += bf[i * 64 + tt] * Wqs[t * 64 + tt];
        } else if (t < 128) {
            int e = t - 64; v = bk[e];
            for (int tt = 0; tt < 64; tt++) v += bf[i * 64 + tt] * Wks[e * 64 + tt];
        } else if (t < 132) {
            int h = t - 128; v = g_dv[h];
            for (int tt = 0; tt < 64; tt++) v += bf[i * 64 + tt] * cvs[h * 64 + tt];
        } else v = 0.f;
        g_bcomb[i * NCB + t] = v;
    }
}

// middle-layer weights -> fragment blobs (hi/lo split). grid 34*8 blocks.
__global__ void setup_midblob_kernel(const float* __restrict__ Wm)
{
    int mat = blockIdx.x >> 3, part = blockIdx.x & 7;
    const float* W = Wm + (size_t)mat * 65536;
    uint2* dst = g_Bmid + (size_t)mat * 32768;
    for (int idx = part * 4096 + threadIdx.x; idx < (part + 1) * 4096; idx += 256) {
        int lane = idx & 31;
        int ntl  = (idx >> 5) & 15;
        int s    = (idx >> 9) & 1;
        int kt   = (idx >> 10) & 15;
        int h    = (idx >> 14) & 1;
        int n  = (h * 16 + ntl) * 8 + (lane >> 2);
        int k0 = kt * 16 + (lane & 3) * 2;
        float w0 = W[(k0 + 0) * 256 + n], w1 = W[(k0 + 1) * 256 + n];
        float w8 = W[(k0 + 8) * 256 + n], w9 = W[(k0 + 9) * 256 + n];
        uint32_t p0 = pk(w0, w1), p1 = pk(w8, w9);
        if (s == 0) {
            dst[idx] = make_uint2(p0, p1);
        } else {
            dst[idx] = make_uint2(pk(relo(p0, w0), rehi(p0, w1)),
                                  pk(relo(p1, w8), rehi(p1, w9)));
        }
    }
}

// final combined weights -> fragment blobs. grid 17*4 blocks. (after setup2)
__global__ void setup_finblob_kernel()
{
    int i = blockIdx.x >> 2, part = blockIdx.x & 3;
    uint2* dst = g_Bfin + (size_t)i * 17408;
    int lo_i = part * 4352, hi_i = lo_i + 4352;
    for (int idx = lo_i + threadIdx.x; idx < hi_i; idx += 256) {
        int lane = idx & 31;
        int q  = idx >> 5;
        int nt = q % 17;
        int q2 = q / 17;
        int s  = q2 & 1;
        int kt = q2 >> 1;
        int n  = nt * 8 + (lane >> 2);
        int k0 = kt * 16 + (lane & 3) * 2;
        const float* W = g_Wcomb + (size_t)i * 256 * NCB;
        float w0 = W[(k0 + 0) * NCB + n], w1 = W[(k0 + 1) * NCB + n];
        float w8 = W[(k0 + 8) * NCB + n], w9 = W[(k0 + 9) * NCB + n];
        uint32_t p0 = pk(w0, w1), p1 = pk(w8, w9);
        if (s == 0) {
            dst[idx] = make_uint2(p0, p1);
        } else {
            dst[idx] = make_uint2(pk(relo(p0, w0), rehi(p0, w1)),
                                  pk(relo(p1, w8), rehi(p1, w9)));
        }
    }
}

// ============================ main kernel ============================
__device__ __forceinline__ void stage_chunk(char* smem, int g, int i, int t)
{
    char* dst = smem + SM_BBUF + (g & 1) * 8704;
    if (g < 64) {
        int layer = g >> 5, rem = g & 31;   // rem = h*16+kt
        const char* src = (const char*)g_Bmid + ((size_t)(layer * Dn + i) * 32768 + (size_t)rem * 1024) * 8;
        #pragma unroll
        for (int u = 0; u < 2; u++)
            cpa16(dst + (t + u * 256) * 16, src + (t + u * 256) * 16);
    } else {
        const char* src = (const char*)g_Bfin + ((size_t)i * 17408 + (size_t)(g - 64) * 1088) * 8;
        #pragma unroll
        for (int u = 0; u < 3; u++) {
            int o = t + u * 256;
            if (o < 544) cpa16(dst + o * 16, src + o * 16);
        }
    }
}

__global__ void __launch_bounds__(256) subnet_mma_kernel(
    const float* __restrict__ x, const float* __restrict__ W1,
    const float* __restrict__ b1, const float* __restrict__ bm)
{
    extern __shared__ char smem[];
    float* xs   = (float*)(smem + SM_X);
    float* w1s  = (float*)(smem + SM_W1);
    float* b1s  = (float*)(smem + SM_B1);
    float* bm0s = (float*)(smem + SM_BM0);
    float* bm1s = (float*)(smem + SM_BM1);
    float* bcs  = (float*)(smem + SM_BC);

    const int t = threadIdx.x, w = t >> 5, lane = t & 31;
    const int gr = lane >> 2, c = lane & 3;
    const int i  = blockIdx.y, r0 = blockIdx.x * 128;

    // stage chunk 0 ASAP
    stage_chunk(smem, 0, i, t);
    CPCOMMIT();

    // stage constants
    if (t < 128) xs[t] = x[(size_t)(r0 + t) * Dn + i];
    w1s[t]  = W1[i * 256 + t];
    b1s[t]  = b1[i * 256 + t];
    bm0s[t] = bm[(0 * Dn + i) * 256 + t];
    bm1s[t] = bm[(1 * Dn + i) * 256 + t];
    if (t < NCB) bcs[t] = g_bcomb[i * NCB + t];
    __syncthreads();

    // ---- first layer: outer product -> A fragments (hi in regs, lo in smem buf0) ----
    uint32_t Ahi[16][4];
    {
        float xa = xs[w * 16 + gr];
        float xb = xs[w * 16 + gr + 8];
        #pragma unroll
        for (int kt = 0; kt < 16; kt++) {
            int c0 = kt * 16 + 2 * c;
            float W0 = w1s[c0], W1v = w1s[c0 + 1], W8 = w1s[c0 + 8], W9 = w1s[c0 + 9];
            float B0 = b1s[c0], B1v = b1s[c0 + 1], B8 = b1s[c0 + 8], B9 = b1s[c0 + 9];
            float v0 = lrelu(fmaf(xa, W0, B0)),  v1 = lrelu(fmaf(xa, W1v, B1v));
            float v2 = lrelu(fmaf(xb, W0, B0)),  v3 = lrelu(fmaf(xb, W1v, B1v));
            float v4 = lrelu(fmaf(xa, W8, B8)),  v5 = lrelu(fmaf(xa, W9, B9));
            float v6 = lrelu(fmaf(xb, W8, B8)),  v7 = lrelu(fmaf(xb, W9, B9));
            uint32_t h0 = pk(v0, v1), h1 = pk(v2, v3), h2 = pk(v4, v5), h3 = pk(v6, v7);
            Ahi[kt][0] = h0; Ahi[kt][1] = h1; Ahi[kt][2] = h2; Ahi[kt][3] = h3;
            uint4 lo4;
            lo4.x = pk(relo(h0, v0), rehi(h0, v1));
            lo4.y = pk(relo(h1, v2), rehi(h1, v3));
            lo4.z = pk(relo(h2, v4), rehi(h2, v5));
            lo4.w = pk(relo(h3, v6), rehi(h3, v7));
            *(uint4*)(smem + SM_ALO + 0 * 65536 + kt * 4096 + w * 512 + lane * 16) = lo4;
        }
    }

    // ---- two middle 256x256 layers ----
    #pragma unroll 1
    for (int layer = 0; layer < 2; layer++) {
        uint32_t Anext[16][4];
        const float* bmls = (layer == 0) ? bm0s : bm1s;
        const int lread = layer & 1, lwrite = lread ^ 1;

        #pragma unroll
        for (int h = 0; h < 2; h++) {
            float acc[16][4];
            #pragma unroll
            for (int n_ = 0; n_ < 16; n_++)
                #pragma unroll
                for (int r = 0; r < 4; r++) acc[n_][r] = 0.f;

            #pragma unroll
            for (int kt = 0; kt < 16; kt++) {
                const int g = layer * 32 + h * 16 + kt;
                __syncthreads();
                if (g < 79) { stage_chunk(smem, g + 1, i, t); CPCOMMIT(); CPWAIT(1); }
                else        { CPWAIT(0); }
                __syncthreads();

                const char* bb = smem + SM_BBUF + (g & 1) * 8704;
                uint4 a4 = *(const uint4*)(smem + SM_ALO + lread * 65536 + kt * 4096 + w * 512 + lane * 16);
                uint32_t al[4] = {a4.x, a4.y, a4.z, a4.w};

                #pragma unroll
                for (int ntl = 0; ntl < 16; ntl++) {
                    uint2 bh = *(const uint2*)(bb + (ntl * 32 + lane) * 8);
                    uint2 bl = *(const uint2*)(bb + 4096 + (ntl * 32 + lane) * 8);
                    mma16816(acc[ntl], Ahi[kt], bh.x, bh.y);
                    mma16816(acc[ntl], Ahi[kt], bl.x, bl.y);
                    mma16816(acc[ntl], al,      bh.x, bh.y);
                }
            }

            // epilogue: bias + lrelu, C-frags -> next-layer A-frags
            #pragma unroll
            for (int j = 0; j < 8; j++) {
                int nt0 = 2 * j, nt1 = 2 * j + 1;
                int cb = 128 * h + 16 * j + 2 * c;
                float2 bb0 = *(const float2*)(bmls + cb);
                float2 bb1 = *(const float2*)(bmls + cb + 8);
                float v0 = lrelu(acc[nt0][0] + bb0.x), v1 = lrelu(acc[nt0][1] + bb0.y);
                float v2 = lrelu(acc[nt0][2] + bb0.x), v3 = lrelu(acc[nt0][3] + bb0.y);
                float v4 = lrelu(acc[nt1][0] + bb1.x), v5 = lrelu(acc[nt1][1] + bb1.y);
                float v6 = lrelu(acc[nt1][2] + bb1.x), v7 = lrelu(acc[nt1][3] + bb1.y);
                uint32_t h0 = pk(v0, v1), h1 = pk(v2, v3), h2 = pk(v4, v5), h3 = pk(v6, v7);
                Anext[8 * h + j][0] = h0; Anext[8 * h + j][1] = h1;
                Anext[8 * h + j][2] = h2; Anext[8 * h + j][3] = h3;
                uint4 lo4;
                lo4.x = pk(relo(h0, v0), rehi(h0, v1));
                lo4.y = pk(relo(h1, v2), rehi(h1, v3));
                lo4.z = pk(relo(h2, v4), rehi(h2, v5));
                lo4.w = pk(relo(h3, v6), rehi(h3, v7));
                *(uint4*)(smem + SM_ALO + lwrite * 65536 + (8 * h + j) * 4096 + w * 512 + lane * 16) = lo4;
            }
        }

        #pragma unroll
        for (int q = 0; q < 16; q++)
            #pragma unroll
            for (int r = 0; r < 4; r++) Ahi[q][r] = Anext[q][r];
    }

    // ---- final layer: 256 -> 136 (q | k | vs) ----
    {
        float fac[17][4];
        #pragma unroll
        for (int n_ = 0; n_ < 17; n_++)
            #pragma unroll
            for (int r = 0; r < 4; r++) fac[n_][r] = 0.f;

        #pragma unroll
        for (int kt = 0; kt < 16; kt++) {
            const int g = 64 + kt;
            __syncthreads();
            if (g < 79) { stage_chunk(smem, g + 1, i, t); CPCOMMIT(); CPWAIT(1); }
            else        { CPWAIT(0); }
            __syncthreads();

            const char* bb = smem + SM_BBUF + (g & 1) * 8704;
            uint4 a4 = *(const uint4*)(smem + SM_ALO + 0 * 65536 + kt * 4096 + w * 512 + lane * 16);
            uint32_t al[4] = {a4.x, a4.y, a4.z, a4.w};

            #pragma unroll
            for (int nt = 0; nt < 17; nt++) {
                uint2 bh = *(const uint2*)(bb + (nt * 32 + lane) * 8);
                uint2 bl = *(const uint2*)(bb + 4352 + (nt * 32 + lane) * 8);
                mma16816(fac[nt], Ahi[kt], bh.x, bh.y);
                mma16816(fac[nt], Ahi[kt], bl.x, bl.y);
                mma16816(fac[nt], al,      bh.x, bh.y);
            }
        }

        // epilogue: bias + scatter to g_q / g_k / g_vs
        const int row0 = r0 + w * 16 + gr, row1 = row0 + 8;
        #pragma unroll
        for (int nt = 0; nt < 17; nt++) {
            int col = nt * 8 + 2 * c;
            float2 bb = *(const float2*)(bcs + col);
            float2 o0 = make_float2(fac[nt][0] + bb.x, fac[nt][1] + bb.y);
            float2 o1 = make_float2(fac[nt][2] + bb.x, fac[nt][3] + bb.y);
            if (nt < 8) {
                *(float2*)&g_q[((size_t)row0 * Dn + i) * En + col] = o0;
                *(float2*)&g_q[((size_t)row1 * Dn + i) * En + col] = o1;
            } else if (nt < 16) {
                *(float2*)&g_k[((size_t)row0 * Dn + i) * En + (col - 64)] = o0;
                *(float2*)&g_k[((size_t)row1 * Dn + i) * En + (col - 64)] = o1;
            } else if (c < 2) {
                *(float2*)&g_vs[((size_t)row0 * Dn + i) * 4 + (col - 128)] = o0;
                *(float2*)&g_vs[((size_t)row1 * Dn + i) * 4 + (col - 128)] = o1;
            }
        }
    }
}

// ============================ attention-lite kernel ============================
#define QS2 68
__global__ void __launch_bounds__(256, 2) attn_kernel(float* __restrict__ out)
{
    extern __shared__ float smemf[];
    const int t = threadIdx.x, wid = t >> 5, lane = t & 31;
    float* qs  = smemf + wid * (2 * Dn * QS2 + 68);
    float* ks  = qs + Dn * QS2;
    float* vss = ks + Dn * QS2;

    const int row = blockIdx.x * 8 + wid;
    const float* qr = g_q + (size_t)row * (Dn * En);
    const float* kr = g_k + (size_t)row * (Dn * En);

    #pragma unroll
    for (int u = 0; u < 34; u++) {
        int o = u * 32 + lane;
        int ii = o >> 6, e = o & 63;
        qs[ii * QS2 + e] = qr[o];
        ks[ii * QS2 + e] = kr[o];
    }
    #pragma unroll
    for (int u = 0; u < 3; u++) {
        int p = u * 32 + lane;
        if (p < 68) vss[p] = g_vs[(size_t)row * 68 + p];
    }
    __syncwarp();

    float partial = 0.f;
    #pragma unroll
    for (int u = 0; u < 3; u++) {
        int p = u * 32 + lane;
        if (p < 68) {
            int h = p / 17, i1 = p - h * 17;
            const float* qv = qs + i1 * QS2 + h * 16;
            float s[17], smax = -1e30f;
            #pragma unroll
            for (int i2 = 0; i2 < 17; i2++) {
                const float* kv = ks + i2 * QS2 + h * 16;
                float d = 0.f;
                #pragma unroll
                for (int j = 0; j < 16; j++) d += qv[j] * kv[j];
                d *= 0.25f;
                s[i2] = d;
                smax = fmaxf(smax, d);
            }
            float den = 0.f, num = 0.f;
            #pragma unroll
            for (int i2 = 0; i2 < 17; i2++) {
                float e = __expf(s[i2] - smax);
                den += e;
                num += e * vss[i2 * 4 + h];
            }
            partial += num / den;
        }
    }
    #pragma unroll
    for (int off = 16; off; off >>= 1)
        partial += __shfl_down_sync(0xffffffffu, partial, off);
    if (lane == 0) out[row] = lrelu(partial * (1.f / 17.f) + g_const);
}

// ---------------------------------------------------------------------------
extern "C" void kernel_launch(void* const* d_in, const int* in_sizes, int n_in,
                              void* d_out, int out_size)
{
    const float* x   = (const float*)d_in[0];
    const float* W1  = (const float*)d_in[1];
    const float* b1  = (const float*)d_in[2];
    const float* Wm  = (const float*)d_in[3];
    const float* bm  = (const float*)d_in[4];
    const float* Wf  = (const float*)d_in[5];
    const float* bf  = (const float*)d_in[6];
    const float* Wq  = (const float*)d_in[7];
    const float* bq  = (const float*)d_in[8];
    const float* Wk  = (const float*)d_in[9];
    const float* bk  = (const float*)d_in[10];
    const float* Wv  = (const float*)d_in[11];
    const float* bv  = (const float*)d_in[12];
    const float* Wo  = (const float*)d_in[13];
    const float* bo  = (const float*)d_in[14];
    const float* Wfc = (const float*)d_in[15];
    const float* bfc = (const float*)d_in[16];
    float* out = (float*)d_out;

    const int k2_smem = 8 * (2 * Dn * QS2 + 68) * (int)sizeof(float);

    cudaFuncSetAttribute(subnet_mma_kernel, cudaFuncAttributeMaxDynamicSharedMemorySize, SM_TOTAL);
    cudaFuncSetAttribute(attn_kernel,       cudaFuncAttributeMaxDynamicSharedMemorySize, k2_smem);

    setup1_kernel<<<1, 64>>>(Wv, bv, Wo, bo, Wfc, bfc);
    setup2_kernel<<<Dn, 256>>>(Wf, bf, Wq, bq, Wk, bk);
    setup_midblob_kernel<<<2 * Dn * 8, 256>>>(Wm);
    setup_finblob_kernel<<<Dn * 4, 256>>>();

    dim3 g1(Bn / 128, Dn);
    subnet_mma_kernel<<<g1, 256, SM_TOTAL>>>(x, W1, b1, bm);

    attn_kernel<<<Bn / 8, 256, k2_smem>>>(out);
}

// round 6
// speedup vs baseline: 4.4680x; 1.1771x over previous
#include <cuda_runtime.h>
#include <cuda_fp16.h>
#include <cstdint>

#define SLOPE 0.01f
#define Dn 17
#define Hn 256
#define En 64
#define NCB 136
#define Bn 16384

// smem byte offsets (main kernel)
#define SM_X     0        // 128 floats
#define SM_W1    512      // 256 floats
#define SM_B1    1536     // 256 floats
#define SM_BM0   2560     // 256 floats
#define SM_BM1   3584     // 256 floats
#define SM_BC    4608     // 136 floats
#define SM_BBUF  5248     // 2 x 8704 B double buffer
#define SM_TOTAL (5248 + 2 * 8704)

// ---- static device scratch (no allocation) ----
__device__ float g_q [(size_t)Bn * Dn * En];
__device__ float g_k [(size_t)Bn * Dn * En];
__device__ float g_vs[(size_t)Bn * Dn * 4];
__device__ float g_Wcomb[Dn * Hn * NCB];
__device__ float g_bcomb[Dn * NCB];
__device__ float g_cv[4 * En];
__device__ float g_dv[4];
__device__ float g_const;
// fragment-ordered fp16 weight blobs; each uint4 = {hi.b0, hi.b1, lo.b0, lo.b1}
// mid: per mat (l*17+i): [h*16+kt][ntl][lane] -> 16384 uint4
__device__ uint4 g_Bmid[(size_t)2 * Dn * 16384];
// fin: per i: [kt][nt][lane] -> 8704 uint4
__device__ uint4 g_Bfin[(size_t)Dn * 8704];

__device__ __forceinline__ float lrelu(float v) { return v >= 0.f ? v : SLOPE * v; }

// pack two f32 -> f16x2 (first arg -> bits[15:0], second -> bits[31:16])
__device__ __forceinline__ uint32_t pkh(float lo, float hi) {
    uint32_t r;
    asm("cvt.rn.f16x2.f32 %0, %1, %2;" : "=r"(r) : "f"(hi), "f"(lo));
    return r;
}
__device__ __forceinline__ float f16res(float v) {
    return v - __half2float(__float2half_rn(v));
}

__device__ __forceinline__ void mma16816(float* d, const uint32_t* a, uint32_t b0, uint32_t b1) {
    asm volatile(
        "mma.sync.aligned.m16n8k16.row.col.f32.f16.f16.f32 "
        "{%0,%1,%2,%3}, {%4,%5,%6,%7}, {%8,%9}, {%0,%1,%2,%3};"
        : "+f"(d[0]), "+f"(d[1]), "+f"(d[2]), "+f"(d[3])
        : "r"(a[0]), "r"(a[1]), "r"(a[2]), "r"(a[3]), "r"(b0), "r"(b1));
}

__device__ __forceinline__ void cpa16(void* sdst, const void* gsrc) {
    uint32_t s = (uint32_t)__cvta_generic_to_shared(sdst);
    asm volatile("cp.async.cg.shared.global [%0], [%1], 16;" :: "r"(s), "l"(gsrc));
}
#define CPCOMMIT() asm volatile("cp.async.commit_group;")
#define CPWAIT(n)  asm volatile("cp.async.wait_group %0;" :: "n"(n))

// ============================ setup kernels ============================
__global__ void setup1_kernel(const float* __restrict__ Wv, const float* __restrict__ bv,
                              const float* __restrict__ Wo, const float* __restrict__ bo,
                              const float* __restrict__ Wfc, const float* __restrict__ bfc)
{
    __shared__ float us[64];
    int t = threadIdx.x;
    float s = 0.f;
    for (int e = 0; e < 64; e++) s += Wo[e * 64 + t] * Wfc[e];
    us[t] = s;
    __syncthreads();
    for (int h = 0; h < 4; h++) {
        float c = 0.f;
        for (int j = 0; j < 16; j++) c += Wv[(h * 16 + j) * 64 + t] * us[h * 16 + j];
        g_cv[h * 64 + t] = c;
    }
    if (t < 4) {
        float dsum = 0.f;
        for (int j = 0; j < 16; j++) dsum += bv[t * 16 + j] * us[t * 16 + j];
        g_dv[t] = dsum;
    }
    if (t == 0) {
        float c = bfc[0];
        for (int e = 0; e < 64; e++) c += bo[e] * Wfc[e];
        g_const = c;
    }
}

__global__ void setup2_kernel(const float* __restrict__ Wf, const float* __restrict__ bf,
                              const float* __restrict__ Wq, const float* __restrict__ bq,
                              const float* __restrict__ Wk, const float* __restrict__ bk)
{
    __shared__ float Wqs[4096], Wks[4096], cvs[256];
    int t = threadIdx.x, i = blockIdx.x;
    #pragma unroll
    for (int u = 0; u < 16; u++) {
        int idx = t + 256 * u;
        Wqs[idx] = Wq[idx];
        Wks[idx] = Wk[idx];
    }
    cvs[t] = g_cv[t];
    __syncthreads();

    int k = t;
    float wf[64];
    #pragma unroll
    for (int tt = 0; tt < 64; tt++) wf[tt] = Wf[((size_t)i * 256 + k) * 64 + tt];
    float* dst = g_Wcomb + ((size_t)i * 256 + k) * NCB;
    for (int e = 0; e < 64; e++) {
        float sq = 0.f, sk = 0.f;
        #pragma unroll
        for (int tt = 0; tt < 64; tt++) { sq += wf[tt] * Wqs[e * 64 + tt]; sk += wf[tt] * Wks[e * 64 + tt]; }
        dst[e] = sq; dst[64 + e] = sk;
    }
    #pragma unroll
    for (int h = 0; h < 4; h++) {
        float sv = 0.f;
        #pragma unroll
        for (int tt = 0; tt < 64; tt++) sv += wf[tt] * cvs[h * 64 + tt];
        dst[128 + h] = sv;
    }
    dst[132] = dst[133] = dst[134] = dst[135] = 0.f;

    if (t < NCB) {
        float v;
        if (t < 64) {
            v = bq[t];
            for (int tt = 0; tt < 64; tt++) v += bf[i * 64 + tt] * Wqs[t * 64 + tt];
        } else if (t < 128) {
            int e = t - 64; v = bk[e];
            for (int tt = 0; tt < 64; tt++) v += bf[i * 64 + tt] * Wks[e * 64 + tt];
        } else if (t < 132) {
            int h = t - 128; v = g_dv[h];
            for (int tt = 0; tt < 64; tt++) v += bf[i * 64 + tt] * cvs[h * 64 + tt];
        } else v = 0.f;
        g_bcomb[i * NCB + t] = v;
    }
}

// middle-layer weights -> fp16 hi/lo fragment blobs. grid 34*8 blocks.
__global__ void setup_midblob_kernel(const float* __restrict__ Wm)
{
    int mat = blockIdx.x >> 3, part = blockIdx.x & 7;
    const float* W = Wm + (size_t)mat * 65536;
    uint4* dst = g_Bmid + (size_t)mat * 16384;
    for (int idx = part * 2048 + threadIdx.x; idx < (part + 1) * 2048; idx += 256) {
        int lane = idx & 31;
        int ntl  = (idx >> 5) & 15;
        int kt   = (idx >> 9) & 15;
        int h    = (idx >> 13) & 1;
        int n  = (h * 16 + ntl) * 8 + (lane >> 2);
        int k0 = kt * 16 + (lane & 3) * 2;
        float w0 = W[(k0 + 0) * 256 + n], w1 = W[(k0 + 1) * 256 + n];
        float w8 = W[(k0 + 8) * 256 + n], w9 = W[(k0 + 9) * 256 + n];
        uint4 v;
        v.x = pkh(w0, w1);
        v.y = pkh(w8, w9);
        v.z = pkh(f16res(w0), f16res(w1));
        v.w = pkh(f16res(w8), f16res(w9));
        dst[idx] = v;
    }
}

// final combined weights -> fp16 hi/lo fragment blobs. grid 17*2 blocks.
__global__ void setup_finblob_kernel()
{
    int i = blockIdx.x >> 1, part = blockIdx.x & 1;
    uint4* dst = g_Bfin + (size_t)i * 8704;
    int lo_i = part * 4352, hi_i = lo_i + 4352;
    const float* W = g_Wcomb + (size_t)i * 256 * NCB;
    for (int idx = lo_i + threadIdx.x; idx < hi_i; idx += 256) {
        int lane = idx & 31;
        int q  = idx >> 5;
        int nt = q % 17;
        int kt = q / 17;
        int n  = nt * 8 + (lane >> 2);
        int k0 = kt * 16 + (lane & 3) * 2;
        float w0 = W[(k0 + 0) * NCB + n], w1 = W[(k0 + 1) * NCB + n];
        float w8 = W[(k0 + 8) * NCB + n], w9 = W[(k0 + 9) * NCB + n];
        uint4 v;
        v.x = pkh(w0, w1);
        v.y = pkh(w8, w9);
        v.z = pkh(f16res(w0), f16res(w1));
        v.w = pkh(f16res(w8), f16res(w9));
        dst[idx] = v;
    }
}

// ============================ main kernel ============================
__device__ __forceinline__ void stage_chunk(char* smem, int g, int i, int t)
{
    char* dst = smem + SM_BBUF + (g & 1) * 8704;
    if (g < 64) {
        int layer = g >> 5, rem = g & 31;   // rem = h*16+kt
        const char* src = (const char*)(g_Bmid + (size_t)(layer * Dn + i) * 16384 + (size_t)rem * 512);
        cpa16(dst + t * 16, src + t * 16);
        cpa16(dst + (t + 256) * 16, src + (t + 256) * 16);
    } else {
        const char* src = (const char*)(g_Bfin + (size_t)i * 8704 + (size_t)(g - 64) * 544);
        #pragma unroll
        for (int u = 0; u < 3; u++) {
            int o = t + u * 256;
            if (o < 544) cpa16(dst + o * 16, src + o * 16);
        }
    }
}

__global__ void __launch_bounds__(256, 1) subnet_mma_kernel(
    const float* __restrict__ x, const float* __restrict__ W1,
    const float* __restrict__ b1, const float* __restrict__ bm)
{
    extern __shared__ char smem[];
    float* xs   = (float*)(smem + SM_X);
    float* w1s  = (float*)(smem + SM_W1);
    float* b1s  = (float*)(smem + SM_B1);
    float* bm0s = (float*)(smem + SM_BM0);
    float* bm1s = (float*)(smem + SM_BM1);
    float* bcs  = (float*)(smem + SM_BC);

    const int t = threadIdx.x, w = t >> 5, lane = t & 31;
    const int gr = lane >> 2, c = lane & 3;
    const int i  = blockIdx.y, r0 = blockIdx.x * 128;

    // stage chunk 0 ASAP
    stage_chunk(smem, 0, i, t);
    CPCOMMIT();

    // stage constants
    if (t < 128) xs[t] = x[(size_t)(r0 + t) * Dn + i];
    w1s[t]  = W1[i * 256 + t];
    b1s[t]  = b1[i * 256 + t];
    bm0s[t] = bm[(0 * Dn + i) * 256 + t];
    bm1s[t] = bm[(1 * Dn + i) * 256 + t];
    if (t < NCB) bcs[t] = g_bcomb[i * NCB + t];
    __syncthreads();

    // ---- first layer: outer product -> A fragments (fp16, regs only) ----
    uint32_t Ahi[16][4];
    {
        float xa = xs[w * 16 + gr];
        float xb = xs[w * 16 + gr + 8];
        #pragma unroll
        for (int kt = 0; kt < 16; kt++) {
            int c0 = kt * 16 + 2 * c;
            float W0 = w1s[c0], W1v = w1s[c0 + 1], W8 = w1s[c0 + 8], W9 = w1s[c0 + 9];
            float B0 = b1s[c0], B1v = b1s[c0 + 1], B8 = b1s[c0 + 8], B9 = b1s[c0 + 9];
            Ahi[kt][0] = pkh(lrelu(fmaf(xa, W0, B0)), lrelu(fmaf(xa, W1v, B1v)));
            Ahi[kt][1] = pkh(lrelu(fmaf(xb, W0, B0)), lrelu(fmaf(xb, W1v, B1v)));
            Ahi[kt][2] = pkh(lrelu(fmaf(xa, W8, B8)), lrelu(fmaf(xa, W9, B9)));
            Ahi[kt][3] = pkh(lrelu(fmaf(xb, W8, B8)), lrelu(fmaf(xb, W9, B9)));
        }
    }

    // ---- two middle 256x256 layers ----
    #pragma unroll 1
    for (int layer = 0; layer < 2; layer++) {
        uint32_t Anext[16][4];
        const float* bmls = (layer == 0) ? bm0s : bm1s;

        #pragma unroll
        for (int h = 0; h < 2; h++) {
            float acc[16][4];
            #pragma unroll
            for (int n_ = 0; n_ < 16; n_++)
                #pragma unroll
                for (int r = 0; r < 4; r++) acc[n_][r] = 0.f;

            #pragma unroll
            for (int kt = 0; kt < 16; kt++) {
                const int g = layer * 32 + h * 16 + kt;
                __syncthreads();
                if (g < 79) { stage_chunk(smem, g + 1, i, t); CPCOMMIT(); CPWAIT(1); }
                else        { CPWAIT(0); }
                __syncthreads();

                const char* bb = smem + SM_BBUF + (g & 1) * 8704;
                #pragma unroll
                for (int ntl = 0; ntl < 16; ntl++) {
                    uint4 b4 = *(const uint4*)(bb + (ntl * 32 + lane) * 16);
                    mma16816(acc[ntl], Ahi[kt], b4.x, b4.y);   // A * W_hi
                    mma16816(acc[ntl], Ahi[kt], b4.z, b4.w);   // A * W_lo
                }
            }

            // epilogue: bias + lrelu, C-frags -> next-layer A-frags (fp16)
            #pragma unroll
            for (int j = 0; j < 8; j++) {
                int nt0 = 2 * j, nt1 = 2 * j + 1;
                int cb = 128 * h + 16 * j + 2 * c;
                float2 bb0 = *(const float2*)(bmls + cb);
                float2 bb1 = *(const float2*)(bmls + cb + 8);
                Anext[8 * h + j][0] = pkh(lrelu(acc[nt0][0] + bb0.x), lrelu(acc[nt0][1] + bb0.y));
                Anext[8 * h + j][1] = pkh(lrelu(acc[nt0][2] + bb0.x), lrelu(acc[nt0][3] + bb0.y));
                Anext[8 * h + j][2] = pkh(lrelu(acc[nt1][0] + bb1.x), lrelu(acc[nt1][1] + bb1.y));
                Anext[8 * h + j][3] = pkh(lrelu(acc[nt1][2] + bb1.x), lrelu(acc[nt1][3] + bb1.y));
            }
        }

        #pragma unroll
        for (int q = 0; q < 16; q++)
            #pragma unroll
            for (int r = 0; r < 4; r++) Ahi[q][r] = Anext[q][r];
    }

    // ---- final layer: 256 -> 136 (q | k | vs) ----
    {
        float fac[17][4];
        #pragma unroll
        for (int n_ = 0; n_ < 17; n_++)
            #pragma unroll
            for (int r = 0; r < 4; r++) fac[n_][r] = 0.f;

        #pragma unroll
        for (int kt = 0; kt < 16; kt++) {
            const int g = 64 + kt;
            __syncthreads();
            if (g < 79) { stage_chunk(smem, g + 1, i, t); CPCOMMIT(); CPWAIT(1); }
            else        { CPWAIT(0); }
            __syncthreads();

            const char* bb = smem + SM_BBUF + (g & 1) * 8704;
            #pragma unroll
            for (int nt = 0; nt < 17; nt++) {
                uint4 b4 = *(const uint4*)(bb + (nt * 32 + lane) * 16);
                mma16816(fac[nt], Ahi[kt], b4.x, b4.y);
                mma16816(fac[nt], Ahi[kt], b4.z, b4.w);
            }
        }

        // epilogue: bias + scatter to g_q / g_k / g_vs
        const int row0 = r0 + w * 16 + gr, row1 = row0 + 8;
        #pragma unroll
        for (int nt = 0; nt < 17; nt++) {
            int col = nt * 8 + 2 * c;
            float2 bb = *(const float2*)(bcs + col);
            float2 o0 = make_float2(fac[nt][0] + bb.x, fac[nt][1] + bb.y);
            float2 o1 = make_float2(fac[nt][2] + bb.x, fac[nt][3] + bb.y);
            if (nt < 8) {
                *(float2*)&g_q[((size_t)row0 * Dn + i) * En + col] = o0;
                *(float2*)&g_q[((size_t)row1 * Dn + i) * En + col] = o1;
            } else if (nt < 16) {
                *(float2*)&g_k[((size_t)row0 * Dn + i) * En + (col - 64)] = o0;
                *(float2*)&g_k[((size_t)row1 * Dn + i) * En + (col - 64)] = o1;
            } else if (c < 2) {
                *(float2*)&g_vs[((size_t)row0 * Dn + i) * 4 + (col - 128)] = o0;
                *(float2*)&g_vs[((size_t)row1 * Dn + i) * 4 + (col - 128)] = o1;
            }
        }
    }
}

// ============================ attention-lite kernel ============================
#define QS2 68
__global__ void __launch_bounds__(256, 2) attn_kernel(float* __restrict__ out)
{
    extern __shared__ float smemf[];
    const int t = threadIdx.x, wid = t >> 5, lane = t & 31;
    float* qs  = smemf + wid * (2 * Dn * QS2 + 68);
    float* ks  = qs + Dn * QS2;
    float* vss = ks + Dn * QS2;

    const int row = blockIdx.x * 8 + wid;
    const float* qr = g_q + (size_t)row * (Dn * En);
    const float* kr = g_k + (size_t)row * (Dn * En);

    #pragma unroll
    for (int u = 0; u < 34; u++) {
        int o = u * 32 + lane;
        int ii = o >> 6, e = o & 63;
        qs[ii * QS2 + e] = qr[o];
        ks[ii * QS2 + e] = kr[o];
    }
    #pragma unroll
    for (int u = 0; u < 3; u++) {
        int p = u * 32 + lane;
        if (p < 68) vss[p] = g_vs[(size_t)row * 68 + p];
    }
    __syncwarp();

    float partial = 0.f;
    #pragma unroll
    for (int u = 0; u < 3; u++) {
        int p = u * 32 + lane;
        if (p < 68) {
            int h = p / 17, i1 = p - h * 17;
            const float* qv = qs + i1 * QS2 + h * 16;
            float s[17], smax = -1e30f;
            #pragma unroll
            for (int i2 = 0; i2 < 17; i2++) {
                const float* kv = ks + i2 * QS2 + h * 16;
                float d = 0.f;
                #pragma unroll
                for (int j = 0; j < 16; j++) d += qv[j] * kv[j];
                d *= 0.25f;
                s[i2] = d;
                smax = fmaxf(smax, d);
            }
            float den = 0.f, num = 0.f;
            #pragma unroll
            for (int i2 = 0; i2 < 17; i2++) {
                float e = __expf(s[i2] - smax);
                den += e;
                num += e * vss[i2 * 4 + h];
            }
            partial += num / den;
        }
    }
    #pragma unroll
    for (int off = 16; off; off >>= 1)
        partial += __shfl_down_sync(0xffffffffu, partial, off);
    if (lane == 0) out[row] = lrelu(partial * (1.f / 17.f) + g_const);
}

// ---------------------------------------------------------------------------
extern "C" void kernel_launch(void* const* d_in, const int* in_sizes, int n_in,
                              void* d_out, int out_size)
{
    const float* x   = (const float*)d_in[0];
    const float* W1  = (const float*)d_in[1];
    const float* b1  = (const float*)d_in[2];
    const float* Wm  = (const float*)d_in[3];
    const float* bm  = (const float*)d_in[4];
    const float* Wf  = (const float*)d_in[5];
    const float* bf  = (const float*)d_in[6];
    const float* Wq  = (const float*)d_in[7];
    const float* bq  = (const float*)d_in[8];
    const float* Wk  = (const float*)d_in[9];
    const float* bk  = (const float*)d_in[10];
    const float* Wv  = (const float*)d_in[11];
    const float* bv  = (const float*)d_in[12];
    const float* Wo  = (const float*)d_in[13];
    const float* bo  = (const float*)d_in[14];
    const float* Wfc = (const float*)d_in[15];
    const float* bfc = (const float*)d_in[16];
    float* out = (float*)d_out;

    const int k2_smem = 8 * (2 * Dn * QS2 + 68) * (int)sizeof(float);

    cudaFuncSetAttribute(subnet_mma_kernel, cudaFuncAttributeMaxDynamicSharedMemorySize, SM_TOTAL);
    cudaFuncSetAttribute(attn_kernel,       cudaFuncAttributeMaxDynamicSharedMemorySize, k2_smem);

    setup1_kernel<<<1, 64>>>(Wv, bv, Wo, bo, Wfc, bfc);
    setup2_kernel<<<Dn, 256>>>(Wf, bf, Wq, bq, Wk, bk);
    setup_midblob_kernel<<<2 * Dn * 8, 256>>>(Wm);
    setup_finblob_kernel<<<Dn * 2, 256>>>();

    dim3 g1(Bn / 128, Dn);
    subnet_mma_kernel<<<g1, 256, SM_TOTAL>>>(x, W1, b1, bm);

    attn_kernel<<<Bn / 8, 256, k2_smem>>>(out);
}